// round 1
// baseline (speedup 1.0000x reference)
#include <cuda_runtime.h>
#include <math.h>

#define BATCH 2
#define CIN   256
#define CHID  128
#define TT    128     // tscale
#define NSMP  32      // num_sample
#define CROI  512
#define COUT  128
#define DSC   128     // dscale
#define BO    (BATCH*CROI)   // 1024
#define KDIM  (TT*NSMP)      // 4096
#define NDM   (DSC*TT)       // 16384

// Scratch (static __device__ — allocation-free per harness rules)
__device__ float g_h[BATCH*CHID*TT];            // h[b][c][t]
__device__ float g_w3dT[NSMP*CROI*CHID];        // w3dT[n][o][c]
__device__ float g_PT[(size_t)KDIM*BO];         // P^T[k][bo], k = t*32+n
__device__ float g_M3[(size_t)BO*NDM];          // m3[bo][d*128+m]

// ---------------------------------------------------------------------------
// K1: conv1d(256->128, k=3, pad=1) + bias + ReLU   -> g_h
// grid: (b*128+o) blocks of 128 threads (t)
// ---------------------------------------------------------------------------
__global__ __launch_bounds__(128) void conv1d_kernel(
    const float* __restrict__ x, const float* __restrict__ w,
    const float* __restrict__ bias)
{
    int bo = blockIdx.x;
    int b = bo >> 7, o = bo & 127;
    int t = threadIdx.x;
    __shared__ float ws[CIN*3];
    for (int idx = t; idx < CIN*3; idx += 128) ws[idx] = w[o*CIN*3 + idx];
    __syncthreads();
    const float* xb = x + (size_t)b*CIN*TT;
    float acc = bias[o];
    #pragma unroll 4
    for (int i = 0; i < CIN; ++i) {
        float xm = (t > 0)    ? xb[i*TT + t - 1] : 0.f;
        float xc =              xb[i*TT + t];
        float xp = (t < TT-1) ? xb[i*TT + t + 1] : 0.f;
        acc = fmaf(xm, ws[i*3+0], acc);
        acc = fmaf(xc, ws[i*3+1], acc);
        acc = fmaf(xp, ws[i*3+2], acc);
    }
    g_h[(b*CHID + o)*TT + t] = fmaxf(acc, 0.f);
}

// ---------------------------------------------------------------------------
// K2a: transpose w3d[o][c][n] -> g_w3dT[n][o][c]
// grid (512 o, 4 c-blocks), 256 threads
// ---------------------------------------------------------------------------
__global__ __launch_bounds__(256) void w3d_transpose_kernel(
    const float* __restrict__ w3d)
{
    int o  = blockIdx.x;
    int c0 = blockIdx.y * 32;
    __shared__ float tile[32][33];
    int tn = threadIdx.x & 31;       // n
    int tg = threadIdx.x >> 5;       // 0..7
    for (int cc = tg; cc < 32; cc += 8)
        tile[cc][tn] = w3d[((size_t)(o*CHID + c0 + cc))*NSMP + tn];
    __syncthreads();
    int tc = threadIdx.x & 31;       // c
    for (int nn = tg; nn < 32; nn += 8)
        g_w3dT[((size_t)(nn*CROI + o))*CHID + c0 + tc] = tile[tc][nn];
}

// ---------------------------------------------------------------------------
// K2b: P^T[(t*32+n)][b*512+o] = sum_c w3dT[n][o][c] * h[b][c][t]
// GEMM per (b, n, o-tile): [128 o x 128 t], K=128 over c.
// 256 threads, BK=16, micro 8x8.
// ---------------------------------------------------------------------------
__global__ __launch_bounds__(256) void pmat_kernel()
{
    int o0 = blockIdx.x * 128;
    int n  = blockIdx.y;
    int b  = blockIdx.z;
    __shared__ float As[16][132];    // [c][o], padded (transposed stores)
    __shared__ float Bs[16][128];    // [c][t]
    const float* A  = g_w3dT + (size_t)(n*CROI + o0)*CHID;
    const float* Bm = g_h + (size_t)b*CHID*TT;
    int tid = threadIdx.x;
    int ty = tid >> 4, tx = tid & 15;
    float acc[8][8];
    #pragma unroll
    for (int i = 0; i < 8; ++i)
        #pragma unroll
        for (int j = 0; j < 8; ++j) acc[i][j] = 0.f;

    for (int c0 = 0; c0 < CHID; c0 += 16) {
        {   // A tile: 128 rows (o) x 16 cols (c), store transposed
            int r  = tid >> 2;            // 0..63
            int c4 = (tid & 3) * 4;
            #pragma unroll
            for (int p = 0; p < 2; ++p) {
                float4 v = *(const float4*)&A[(r + 64*p)*CHID + c0 + c4];
                As[c4+0][r+64*p] = v.x;
                As[c4+1][r+64*p] = v.y;
                As[c4+2][r+64*p] = v.z;
                As[c4+3][r+64*p] = v.w;
            }
        }
        {   // B tile: 16 rows (c) x 128 cols (t)
            int r  = tid >> 5;            // 0..7
            int c4 = (tid & 31) * 4;
            #pragma unroll
            for (int p = 0; p < 2; ++p) {
                float4 v = *(const float4*)&Bm[(c0 + r + 8*p)*TT + c4];
                *(float4*)&Bs[r + 8*p][c4] = v;
            }
        }
        __syncthreads();
        #pragma unroll
        for (int kk = 0; kk < 16; ++kk) {
            float4 a0 = *(const float4*)&As[kk][ty*8];
            float4 a1 = *(const float4*)&As[kk][ty*8+4];
            float4 b0 = *(const float4*)&Bs[kk][tx*8];
            float4 b1 = *(const float4*)&Bs[kk][tx*8+4];
            float av[8] = {a0.x,a0.y,a0.z,a0.w,a1.x,a1.y,a1.z,a1.w};
            float bv[8] = {b0.x,b0.y,b0.z,b0.w,b1.x,b1.y,b1.z,b1.w};
            #pragma unroll
            for (int i = 0; i < 8; ++i)
                #pragma unroll
                for (int j = 0; j < 8; ++j)
                    acc[i][j] = fmaf(av[i], bv[j], acc[i][j]);
        }
        __syncthreads();
    }
    #pragma unroll
    for (int j = 0; j < 8; ++j) {
        int t = tx*8 + j;
        size_t base = ((size_t)(t*NSMP + n))*BO + b*CROI + o0;
        #pragma unroll
        for (int i = 0; i < 8; ++i)
            g_PT[base + ty*8 + i] = acc[i][j];
    }
}

// ---------------------------------------------------------------------------
// K3: M3[bo][d*128+m] = relu( b3d[o] + sum_k P^T[k][bo] * mask[k][d*128+m] )
// Banded: K restricted to the t-window of (d, m-tile); fully-invalid tiles
// short-circuit to relu(b3d).
// grid: x = d*2 + (m-tile of 64), y = bo-tile of 128. 256 threads.
// ---------------------------------------------------------------------------
__global__ __launch_bounds__(256) void bm_gemm_kernel(
    const float* __restrict__ mask, const float* __restrict__ b3d)
{
    int d   = blockIdx.x >> 1;
    int m0  = (blockIdx.x & 1) * 64;
    int bo0 = blockIdx.y * 128;
    int tid = threadIdx.x;
    int ty  = tid >> 4, tx = tid & 15;   // ty: bo dir (16x8), tx: m dir (16x4)

    if (m0 >= TT - d) {
        // entire m-tile invalid: mask == 0 -> relu(bias)
        #pragma unroll
        for (int i = 0; i < 8; ++i) {
            int row = bo0 + ty*8 + i;
            float v = fmaxf(b3d[row & 511], 0.f);
            size_t base = (size_t)row*NDM + d*TT + m0 + tx*4;
            #pragma unroll
            for (int j = 0; j < 4; ++j) g_M3[base + j] = v;
        }
        return;
    }

    int t_lo = max(0, (int)floorf((float)m0 - (d+1)*0.5f) - 1);
    int t_hi = min(TT-1, (int)ceilf((float)(m0+63) + (float)d + (d+1)*0.5f) + 1);
    int k_lo = t_lo * NSMP, k_hi = (t_hi + 1) * NSMP;

    __shared__ float As[16][128];   // [k][bo]
    __shared__ float Bs[16][68];    // [k][m], padded
    float acc[8][4];
    #pragma unroll
    for (int i = 0; i < 8; ++i)
        #pragma unroll
        for (int j = 0; j < 4; ++j) acc[i][j] = 0.f;

    for (int k0 = k_lo; k0 < k_hi; k0 += 16) {
        {   // A: P^T rows k0..k0+15, cols bo0..bo0+127 (coalesced)
            int kk = tid >> 5;             // 0..7
            int i4 = (tid & 31) * 4;
            #pragma unroll
            for (int p = 0; p < 2; ++p) {
                float4 v = *(const float4*)&g_PT[(size_t)(k0 + kk + 8*p)*BO + bo0 + i4];
                *(float4*)&As[kk + 8*p][i4] = v;
            }
        }
        {   // B: mask rows k0..k0+15, cols d*128+m0 .. +63
            int kk = tid >> 4;             // 0..15
            int j4 = (tid & 15) * 4;
            float4 v = *(const float4*)&mask[(size_t)(k0 + kk)*NDM + d*TT + m0 + j4];
            *(float4*)&Bs[kk][j4] = v;
        }
        __syncthreads();
        #pragma unroll
        for (int kk = 0; kk < 16; ++kk) {
            float4 a0 = *(const float4*)&As[kk][ty*8];
            float4 a1 = *(const float4*)&As[kk][ty*8+4];
            float4 b0 = *(const float4*)&Bs[kk][tx*4];
            float av[8] = {a0.x,a0.y,a0.z,a0.w,a1.x,a1.y,a1.z,a1.w};
            float bv[4] = {b0.x,b0.y,b0.z,b0.w};
            #pragma unroll
            for (int i = 0; i < 8; ++i)
                #pragma unroll
                for (int j = 0; j < 4; ++j)
                    acc[i][j] = fmaf(av[i], bv[j], acc[i][j]);
        }
        __syncthreads();
    }
    #pragma unroll
    for (int i = 0; i < 8; ++i) {
        int row = bo0 + ty*8 + i;
        float bias = b3d[row & 511];
        size_t base = (size_t)row*NDM + d*TT + m0 + tx*4;
        #pragma unroll
        for (int j = 0; j < 4; ++j)
            g_M3[base + j] = fmaxf(acc[i][j] + bias, 0.f);
    }
}

// ---------------------------------------------------------------------------
// K4: out[b][o2][dm] = relu( b2d[o2] + sum_{o<512} w2d[o2][o] * M3[b*512+o][dm] )
// grid: x = dm-tile of 64 (256), y = b (2). 256 threads, BM=128, BN=64, BK=16.
// ---------------------------------------------------------------------------
__global__ __launch_bounds__(256) void out_gemm_kernel(
    const float* __restrict__ w2d, const float* __restrict__ b2d,
    float* __restrict__ out)
{
    int dm0 = blockIdx.x * 64;
    int b   = blockIdx.y;
    __shared__ float As[16][132];   // [k][o2], padded (transposed stores)
    __shared__ float Bs[16][68];    // [k][dm]
    int tid = threadIdx.x;
    int ty = tid >> 4, tx = tid & 15;
    float acc[8][4];
    #pragma unroll
    for (int i = 0; i < 8; ++i)
        #pragma unroll
        for (int j = 0; j < 4; ++j) acc[i][j] = 0.f;

    for (int k0 = 0; k0 < CROI; k0 += 16) {
        {   // A: w2d[o2][k] -> As[k][o2]
            int r  = tid >> 2;            // o2 0..63
            int c4 = (tid & 3) * 4;
            #pragma unroll
            for (int p = 0; p < 2; ++p) {
                float4 v = *(const float4*)&w2d[(size_t)(r + 64*p)*CROI + k0 + c4];
                As[c4+0][r+64*p] = v.x;
                As[c4+1][r+64*p] = v.y;
                As[c4+2][r+64*p] = v.z;
                As[c4+3][r+64*p] = v.w;
            }
        }
        {   // B: M3 rows b*512+k0..+15, cols dm0..+63
            int kk = tid >> 4;
            int j4 = (tid & 15) * 4;
            float4 v = *(const float4*)&g_M3[(size_t)(b*CROI + k0 + kk)*NDM + dm0 + j4];
            *(float4*)&Bs[kk][j4] = v;
        }
        __syncthreads();
        #pragma unroll
        for (int kk = 0; kk < 16; ++kk) {
            float4 a0 = *(const float4*)&As[kk][ty*8];
            float4 a1 = *(const float4*)&As[kk][ty*8+4];
            float4 b0 = *(const float4*)&Bs[kk][tx*4];
            float av[8] = {a0.x,a0.y,a0.z,a0.w,a1.x,a1.y,a1.z,a1.w};
            float bv[4] = {b0.x,b0.y,b0.z,b0.w};
            #pragma unroll
            for (int i = 0; i < 8; ++i)
                #pragma unroll
                for (int j = 0; j < 4; ++j)
                    acc[i][j] = fmaf(av[i], bv[j], acc[i][j]);
        }
        __syncthreads();
    }
    #pragma unroll
    for (int i = 0; i < 8; ++i) {
        int o2 = ty*8 + i;
        float bias = b2d[o2];
        size_t base = (size_t)(b*COUT + o2)*NDM + dm0 + tx*4;
        #pragma unroll
        for (int j = 0; j < 4; ++j)
            out[base + j] = fmaxf(acc[i][j] + bias, 0.f);
    }
}

// ---------------------------------------------------------------------------
// Launch
// Inputs (metadata order): 0:x 1:w_red 2:b_red 3:w3d 4:b3d 5:w2d 6:b2d 7:sample_mask
// ---------------------------------------------------------------------------
extern "C" void kernel_launch(void* const* d_in, const int* in_sizes, int n_in,
                              void* d_out, int out_size)
{
    const float* x     = (const float*)d_in[0];
    const float* w_red = (const float*)d_in[1];
    const float* b_red = (const float*)d_in[2];
    const float* w3d   = (const float*)d_in[3];
    const float* b3d   = (const float*)d_in[4];
    const float* w2d   = (const float*)d_in[5];
    const float* b2d   = (const float*)d_in[6];
    const float* mask  = (const float*)d_in[7];
    float* out = (float*)d_out;

    conv1d_kernel<<<BATCH*CHID, 128>>>(x, w_red, b_red);
    w3d_transpose_kernel<<<dim3(CROI, 4), 256>>>(w3d);
    pmat_kernel<<<dim3(4, NSMP, BATCH), 256>>>();
    bm_gemm_kernel<<<dim3(DSC*2, BO/128), 256>>>(mask, b3d);
    out_gemm_kernel<<<dim3(NDM/64, BATCH), 256>>>(w2d, b2d, out);
}

// round 3
// speedup vs baseline: 4.8473x; 4.8473x over previous
#include <cuda_runtime.h>
#include <math.h>

#define BATCH 2
#define CIN   256
#define CHID  128
#define TT    128     // tscale
#define NSMP  32      // num_sample
#define CROI  512
#define COUT  128
#define DSC   128     // dscale
#define BO    (BATCH*CROI)   // 1024
#define NDM   (DSC*TT)       // 16384

// Scratch
__device__ float g_h[BATCH*CHID*TT];            // h[b][c][t]
__device__ float g_w3dT[NSMP*CROI*CHID];        // w3dT[n][o][c]
__device__ float g_P[(size_t)NSMP*TT*BO];       // P[n][t][bo], bo = b*512+o
__device__ float g_M3[(size_t)BO*NDM];          // m3[bo][d*128+m]

__device__ __forceinline__ unsigned smem_u32(const void* p) {
    return (unsigned)__cvta_generic_to_shared(p);
}
__device__ __forceinline__ void cp_async16(unsigned dst, const void* src, int sz) {
    asm volatile("cp.async.cg.shared.global [%0], [%1], 16, %2;\n"
                 :: "r"(dst), "l"(src), "r"(sz));
}
__device__ __forceinline__ void cp_commit() {
    asm volatile("cp.async.commit_group;\n");
}

// ---------------------------------------------------------------------------
// K1: conv1d(256->128, k=3, pad=1) + bias + ReLU
// ---------------------------------------------------------------------------
__global__ __launch_bounds__(128) void conv1d_kernel(
    const float* __restrict__ x, const float* __restrict__ w,
    const float* __restrict__ bias)
{
    int bo = blockIdx.x;
    int b = bo >> 7, o = bo & 127;
    int t = threadIdx.x;
    __shared__ float ws[CIN*3];
    for (int idx = t; idx < CIN*3; idx += 128) ws[idx] = w[o*CIN*3 + idx];
    __syncthreads();
    const float* xb = x + (size_t)b*CIN*TT;
    float acc = bias[o];
    #pragma unroll 4
    for (int i = 0; i < CIN; ++i) {
        float xm = (t > 0)    ? xb[i*TT + t - 1] : 0.f;
        float xc =              xb[i*TT + t];
        float xp = (t < TT-1) ? xb[i*TT + t + 1] : 0.f;
        acc = fmaf(xm, ws[i*3+0], acc);
        acc = fmaf(xc, ws[i*3+1], acc);
        acc = fmaf(xp, ws[i*3+2], acc);
    }
    g_h[(b*CHID + o)*TT + t] = fmaxf(acc, 0.f);
}

// ---------------------------------------------------------------------------
// K2a: transpose w3d[o][c][n] -> g_w3dT[n][o][c]
// ---------------------------------------------------------------------------
__global__ __launch_bounds__(256) void w3d_transpose_kernel(
    const float* __restrict__ w3d)
{
    int o  = blockIdx.x;
    int c0 = blockIdx.y * 32;
    __shared__ float tile[32][33];
    int tn = threadIdx.x & 31;
    int tg = threadIdx.x >> 5;
    for (int cc = tg; cc < 32; cc += 8)
        tile[cc][tn] = w3d[((size_t)(o*CHID + c0 + cc))*NSMP + tn];
    __syncthreads();
    int tc = threadIdx.x & 31;
    for (int nn = tg; nn < 32; nn += 8)
        g_w3dT[((size_t)(nn*CROI + o))*CHID + c0 + tc] = tile[tc][nn];
}

// ---------------------------------------------------------------------------
// K2b: P[n][t][b*512+o] = sum_c w3dT[n][o][c] * h[b][c][t]
// ---------------------------------------------------------------------------
__global__ __launch_bounds__(256) void pmat_kernel()
{
    int o0 = blockIdx.x * 128;
    int n  = blockIdx.y;
    int b  = blockIdx.z;
    __shared__ float As[16][132];
    __shared__ float Bs[16][128];
    const float* A  = g_w3dT + (size_t)(n*CROI + o0)*CHID;
    const float* Bm = g_h + (size_t)b*CHID*TT;
    int tid = threadIdx.x;
    int ty = tid >> 4, tx = tid & 15;
    float acc[8][8];
    #pragma unroll
    for (int i = 0; i < 8; ++i)
        #pragma unroll
        for (int j = 0; j < 8; ++j) acc[i][j] = 0.f;

    for (int c0 = 0; c0 < CHID; c0 += 16) {
        {
            int r  = tid >> 2;
            int c4 = (tid & 3) * 4;
            #pragma unroll
            for (int p = 0; p < 2; ++p) {
                float4 v = *(const float4*)&A[(r + 64*p)*CHID + c0 + c4];
                As[c4+0][r+64*p] = v.x;
                As[c4+1][r+64*p] = v.y;
                As[c4+2][r+64*p] = v.z;
                As[c4+3][r+64*p] = v.w;
            }
        }
        {
            int r  = tid >> 5;
            int c4 = (tid & 31) * 4;
            #pragma unroll
            for (int p = 0; p < 2; ++p) {
                float4 v = *(const float4*)&Bm[(c0 + r + 8*p)*TT + c4];
                *(float4*)&Bs[r + 8*p][c4] = v;
            }
        }
        __syncthreads();
        #pragma unroll
        for (int kk = 0; kk < 16; ++kk) {
            float4 a0 = *(const float4*)&As[kk][ty*8];
            float4 a1 = *(const float4*)&As[kk][ty*8+4];
            float4 b0 = *(const float4*)&Bs[kk][tx*8];
            float4 b1 = *(const float4*)&Bs[kk][tx*8+4];
            float av[8] = {a0.x,a0.y,a0.z,a0.w,a1.x,a1.y,a1.z,a1.w};
            float bv[8] = {b0.x,b0.y,b0.z,b0.w,b1.x,b1.y,b1.z,b1.w};
            #pragma unroll
            for (int i = 0; i < 8; ++i)
                #pragma unroll
                for (int j = 0; j < 8; ++j)
                    acc[i][j] = fmaf(av[i], bv[j], acc[i][j]);
        }
        __syncthreads();
    }
    #pragma unroll
    for (int j = 0; j < 8; ++j) {
        int t = tx*8 + j;
        size_t base = ((size_t)(n*TT + t))*BO + b*CROI + o0;
        #pragma unroll
        for (int i = 0; i < 8; ++i)
            g_P[base + ty*8 + i] = acc[i][j];
    }
}

// ---------------------------------------------------------------------------
// K3: analytic interp kernel (corrected boundary semantics).
// m3[bo][d*128+m] = relu( b3d + (1/3)*sum_{i=0..95} tap_i )
// tap_i at column m: s = (m - (d+1)/2) + i*(2d+1)/95 (fp64, numpy op order)
//   s >= 0            : (1-f)*P[t0] + f*P[t0+1]   (rows > 127 are zero)
//   -1 < s < 0        : exactly 1.0 * P[0]
//   s <= -1 (incl ==) : 0
// Window rows t<0 are zero-filled. The -1<s<0 case is realized as the base
// tap (f*row0, since row -1 = 0) plus a one-column correction corr_w*row0
// with corr_w = (s* > -1 ? 1 : 0) - f, s* recomputed per-column in fp64.
// Grid: x = m-tile (4), y = d (128), z = bo-tile (8). 256 threads.
// ---------------------------------------------------------------------------
#define WROWS 40
#define WPAD  132
__global__ __launch_bounds__(256) void interp_kernel(const float* __restrict__ b3d)
{
    int m0  = blockIdx.x * 32;
    int d   = blockIdx.y;
    int bo0 = blockIdx.z * 128;
    int tid = threadIdx.x;

    // -------- fully invalid tile: relu(bias) fill --------
    if (m0 >= TT - d) {
        int f4 = tid & 7;
        int r0 = tid >> 3;
        #pragma unroll
        for (int k = 0; k < 4; ++k) {
            int r = r0 + 32*k;
            float v = fmaxf(b3d[(bo0 + r) & 511], 0.f);
            float4 vv = make_float4(v, v, v, v);
            *(float4*)&g_M3[(size_t)(bo0 + r)*NDM + d*TT + m0 + f4*4] = vv;
        }
        return;
    }

    __shared__ float win[2][WROWS*WPAD];
    __shared__ float r0buf[2][128];
    __shared__ int   s_t0[96];
    __shared__ float s_f[96];
    __shared__ int   s_jf[96];
    __shared__ float s_cw[96];

    // -------- fp64 sample table (bit-matches numpy at the -1 boundary) ----
    if (tid < 96) {
        int i = tid;
        double h = 0.5 * (double)(d + 1);
        double p = (2.0*(double)d + 1.0) / 95.0;
        double q = p * (double)i;
        double s = ((double)m0 - h) + q;
        double fs = floor(s);
        int t0 = (int)fs;
        float f = (float)(s - fs);
        s_t0[i] = t0;
        s_f[i]  = f;
        int jf = -1 - t0;                  // column with s in [-1, 0)
        float cw = 0.f;
        if (jf >= 0 && jf < 32) {
            double sstar = ((double)(m0 + jf) - h) + q;  // that column's own fp64
            cw = ((sstar > -1.0) ? 1.0f : 0.0f) - f;
        } else jf = -1;
        s_jf[i] = jf;
        s_cw[i] = cw;
    }
    __syncthreads();

    int bl = tid & 31;     // bo group: 4 bo
    int mg = tid >> 5;     // m group (warp id): columns 4*mg..4*mg+3
    float4 acc0 = make_float4(0,0,0,0), acc1 = acc0, acc2 = acc0, acc3 = acc0;

    // -------- window fill via cp.async: rows t<0 and t>127 are ZERO -------
    int fr = tid >> 5;            // 0..7
    int fc = (tid & 31) * 4;      // float col
    #define FILL(BUF, N) do {                                                  \
        int wlo_ = s_t0[3*(N)];                                                \
        const float* srcb = g_P + ((size_t)(N)*TT)*BO + bo0 + fc;              \
        _Pragma("unroll")                                                      \
        for (int p_ = 0; p_ < 5; ++p_) {                                       \
            int r_ = fr + 8*p_;                                                \
            int t_ = wlo_ + r_;                                                \
            int tc_ = min(max(t_, 0), TT-1);                                   \
            int sz_ = (t_ >= 0 && t_ <= TT-1) ? 16 : 0;                        \
            cp_async16(smem_u32(&win[BUF][r_*WPAD + fc]),                      \
                       srcb + (size_t)tc_*BO, sz_);                            \
        }                                                                      \
        if (fr == 0)                                                           \
            cp_async16(smem_u32(&r0buf[BUF][fc]), srcb, 16);                   \
    } while (0)

    FILL(0, 0);
    cp_commit();

    for (int n = 0; n < NSMP; ++n) {
        int buf = n & 1;
        if (n < NSMP-1) { FILL(buf^1, n+1); cp_commit(); }
        if (n < NSMP-1) { asm volatile("cp.async.wait_group 1;\n" ::: "memory"); }
        else            { asm volatile("cp.async.wait_group 0;\n" ::: "memory"); }
        __syncthreads();

        int wlo = s_t0[3*n];
        const float* wb = &win[buf][0];
        float4 r0v = *(const float4*)&r0buf[buf][4*bl];
        #pragma unroll
        for (int j = 0; j < 3; ++j) {
            int i = 3*n + j;
            int tt = s_t0[i] - wlo;
            float f = s_f[i];
            float w1 = 1.0f - f;
            int rb = tt + 4*mg;
            float4 a0 = *(const float4*)&wb[(rb+0)*WPAD + 4*bl];
            float4 a1 = *(const float4*)&wb[(rb+1)*WPAD + 4*bl];
            float4 a2 = *(const float4*)&wb[(rb+2)*WPAD + 4*bl];
            float4 a3 = *(const float4*)&wb[(rb+3)*WPAD + 4*bl];
            float4 a4 = *(const float4*)&wb[(rb+4)*WPAD + 4*bl];
            acc0.x += w1*a0.x + f*a1.x; acc0.y += w1*a0.y + f*a1.y;
            acc0.z += w1*a0.z + f*a1.z; acc0.w += w1*a0.w + f*a1.w;
            acc1.x += w1*a1.x + f*a2.x; acc1.y += w1*a1.y + f*a2.y;
            acc1.z += w1*a1.z + f*a2.z; acc1.w += w1*a1.w + f*a2.w;
            acc2.x += w1*a2.x + f*a3.x; acc2.y += w1*a2.y + f*a3.y;
            acc2.z += w1*a2.z + f*a3.z; acc2.w += w1*a2.w + f*a3.w;
            acc3.x += w1*a3.x + f*a4.x; acc3.y += w1*a3.y + f*a4.y;
            acc3.z += w1*a3.z + f*a4.z; acc3.w += w1*a3.w + f*a4.w;
            // boundary correction: one column (one warp) gets cw * row0
            int jc = s_jf[i] - 4*mg;       // warp-uniform branch
            if (jc >= 0 && jc < 4) {
                float cw = s_cw[i];
                if (jc == 0) { acc0.x += cw*r0v.x; acc0.y += cw*r0v.y;
                               acc0.z += cw*r0v.z; acc0.w += cw*r0v.w; }
                else if (jc == 1) { acc1.x += cw*r0v.x; acc1.y += cw*r0v.y;
                                    acc1.z += cw*r0v.z; acc1.w += cw*r0v.w; }
                else if (jc == 2) { acc2.x += cw*r0v.x; acc2.y += cw*r0v.y;
                                    acc2.z += cw*r0v.z; acc2.w += cw*r0v.w; }
                else              { acc3.x += cw*r0v.x; acc3.y += cw*r0v.y;
                                    acc3.z += cw*r0v.z; acc3.w += cw*r0v.w; }
            }
        }
        __syncthreads();
    }

    // -------- transpose via smem, add bias, relu, coalesced store ---------
    float* stage = &win[0][0];
    const float third = 1.0f/3.0f;
    acc0.x*=third; acc0.y*=third; acc0.z*=third; acc0.w*=third;
    acc1.x*=third; acc1.y*=third; acc1.z*=third; acc1.w*=third;
    acc2.x*=third; acc2.y*=third; acc2.z*=third; acc2.w*=third;
    acc3.x*=third; acc3.y*=third; acc3.z*=third; acc3.w*=third;
    *(float4*)&stage[(4*mg+0)*WPAD + 4*bl] = acc0;
    *(float4*)&stage[(4*mg+1)*WPAD + 4*bl] = acc1;
    *(float4*)&stage[(4*mg+2)*WPAD + 4*bl] = acc2;
    *(float4*)&stage[(4*mg+3)*WPAD + 4*bl] = acc3;
    __syncthreads();

    int warp = tid >> 5, lane = tid & 31;
    int vlim = TT - 1 - d - m0;            // lane valid iff lane <= vlim
    #pragma unroll
    for (int rr = 0; rr < 16; ++rr) {
        int r = warp*16 + rr;
        float bias = b3d[(bo0 + r) & 511];
        float v = stage[lane*WPAD + r] + bias;
        v = (lane <= vlim) ? fmaxf(v, 0.f) : fmaxf(bias, 0.f);
        g_M3[(size_t)(bo0 + r)*NDM + d*TT + m0 + lane] = v;
    }
}

// ---------------------------------------------------------------------------
// K4: out[b][o2][dm] = relu( b2d[o2] + sum_o w2d[o2][o] * M3[b*512+o][dm] )
// ---------------------------------------------------------------------------
__global__ __launch_bounds__(256) void out_gemm_kernel(
    const float* __restrict__ w2d, const float* __restrict__ b2d,
    float* __restrict__ out)
{
    int dm0 = blockIdx.x * 64;
    int b   = blockIdx.y;
    __shared__ float As[16][132];
    __shared__ float Bs[16][68];
    int tid = threadIdx.x;
    int ty = tid >> 4, tx = tid & 15;
    float acc[8][4];
    #pragma unroll
    for (int i = 0; i < 8; ++i)
        #pragma unroll
        for (int j = 0; j < 4; ++j) acc[i][j] = 0.f;

    for (int k0 = 0; k0 < CROI; k0 += 16) {
        {
            int r  = tid >> 2;
            int c4 = (tid & 3) * 4;
            #pragma unroll
            for (int p = 0; p < 2; ++p) {
                float4 v = *(const float4*)&w2d[(size_t)(r + 64*p)*CROI + k0 + c4];
                As[c4+0][r+64*p] = v.x;
                As[c4+1][r+64*p] = v.y;
                As[c4+2][r+64*p] = v.z;
                As[c4+3][r+64*p] = v.w;
            }
        }
        {
            int kk = tid >> 4;
            int j4 = (tid & 15) * 4;
            float4 v = *(const float4*)&g_M3[(size_t)(b*CROI + k0 + kk)*NDM + dm0 + j4];
            *(float4*)&Bs[kk][j4] = v;
        }
        __syncthreads();
        #pragma unroll
        for (int kk = 0; kk < 16; ++kk) {
            float4 a0 = *(const float4*)&As[kk][ty*8];
            float4 a1 = *(const float4*)&As[kk][ty*8+4];
            float4 b0 = *(const float4*)&Bs[kk][tx*4];
            float av[8] = {a0.x,a0.y,a0.z,a0.w,a1.x,a1.y,a1.z,a1.w};
            float bv[4] = {b0.x,b0.y,b0.z,b0.w};
            #pragma unroll
            for (int i = 0; i < 8; ++i)
                #pragma unroll
                for (int j = 0; j < 4; ++j)
                    acc[i][j] = fmaf(av[i], bv[j], acc[i][j]);
        }
        __syncthreads();
    }
    #pragma unroll
    for (int i = 0; i < 8; ++i) {
        int o2 = ty*8 + i;
        float bias = b2d[o2];
        size_t base = (size_t)(b*COUT + o2)*NDM + dm0 + tx*4;
        #pragma unroll
        for (int j = 0; j < 4; ++j)
            out[base + j] = fmaxf(acc[i][j] + bias, 0.f);
    }
}

// ---------------------------------------------------------------------------
// Inputs: 0:x 1:w_red 2:b_red 3:w3d 4:b3d 5:w2d 6:b2d 7:sample_mask (unused)
// ---------------------------------------------------------------------------
extern "C" void kernel_launch(void* const* d_in, const int* in_sizes, int n_in,
                              void* d_out, int out_size)
{
    const float* x     = (const float*)d_in[0];
    const float* w_red = (const float*)d_in[1];
    const float* b_red = (const float*)d_in[2];
    const float* w3d   = (const float*)d_in[3];
    const float* b3d   = (const float*)d_in[4];
    const float* w2d   = (const float*)d_in[5];
    const float* b2d   = (const float*)d_in[6];
    float* out = (float*)d_out;

    conv1d_kernel<<<BATCH*CHID, 128>>>(x, w_red, b_red);
    w3d_transpose_kernel<<<dim3(CROI, 4), 256>>>(w3d);
    pmat_kernel<<<dim3(4, NSMP, BATCH), 256>>>();
    interp_kernel<<<dim3(4, DSC, BO/128), 256>>>(b3d);
    out_gemm_kernel<<<dim3(NDM/64, BATCH), 256>>>(w2d, b2d, out);
}